// round 1
// baseline (speedup 1.0000x reference)
#include <cuda_runtime.h>
#include <math.h>
#include <stdint.h>

#define NE 8
#define ND 1024
#define NH 2048
#define NO 1024
#define NB 4096

// ---------------- scratch (device globals; no allocation allowed) ----------
__device__ int   g_cnt[NE];
__device__ int   g_tok [NE * NB];
__device__ float g_wt  [NE * NB];
__device__ int   g_slot[NE * NB];
__device__ float g_h1[(size_t)NE * NB * NH];   // 256 MB
__device__ float g_h2[(size_t)NE * NB * NH];   // 256 MB
__device__ float g_part[(size_t)2 * NB * NO];  // 32 MB

struct XPtrs { const float* p[NE]; };

// ---------------- reset (graph replays: counters must re-zero) -------------
__global__ void reset_kernel() {
    if (threadIdx.x < NE) g_cnt[threadIdx.x] = 0;
}

// ---------------- gating: logits + top-2 softmax + scatter -----------------
// block = 256 threads, 128 tokens. thread t: token = t&127, half = t>>7 owns 4 experts.
__global__ void __launch_bounds__(256)
gate_kernel(XPtrs xp, const float* __restrict__ gw, const float* __restrict__ gb) {
    __shared__ float Xs[64][129];  // [k][token], padded vs bank conflicts
    __shared__ float Gs[64][8];
    __shared__ float Ls[128][8];

    const int tid   = threadIdx.x;
    const int token = tid & 127;
    const int half  = tid >> 7;
    const int tok0  = blockIdx.x * 128;

    float acc[4] = {0.f, 0.f, 0.f, 0.f};

    for (int e = 0; e < NE; ++e) {
        const float* __restrict__ xe = xp.p[e];
        for (int dc = 0; dc < ND; dc += 64) {
            // stage X chunk: 128 tokens x 64 dims (transposed into smem)
            #pragma unroll
            for (int i = 0; i < 8; ++i) {
                int idx = tid + i * 256;        // 0..2047
                int r   = idx >> 4;             // token row
                int c   = (idx & 15) * 4;       // dim col
                float4 v = *(const float4*)&xe[(size_t)(tok0 + r) * ND + dc + c];
                Xs[c + 0][r] = v.x; Xs[c + 1][r] = v.y;
                Xs[c + 2][r] = v.z; Xs[c + 3][r] = v.w;
            }
            // stage gate_w chunk: 64 x 8
            if (tid < 128) {
                int r = tid >> 1;
                int c = (tid & 1) * 4;
                float4 v = *(const float4*)&gw[(size_t)(e * ND + dc + r) * NE + c];
                *(float4*)&Gs[r][c] = v;
            }
            __syncthreads();
            #pragma unroll 16
            for (int k = 0; k < 64; ++k) {
                float  a = Xs[k][token];
                float4 g = *(const float4*)&Gs[k][half * 4];
                acc[0] = fmaf(a, g.x, acc[0]);
                acc[1] = fmaf(a, g.y, acc[1]);
                acc[2] = fmaf(a, g.z, acc[2]);
                acc[3] = fmaf(a, g.w, acc[3]);
            }
            __syncthreads();
        }
    }
    #pragma unroll
    for (int j = 0; j < 4; ++j) Ls[token][half * 4 + j] = acc[j] + gb[half * 4 + j];
    __syncthreads();

    if (tid < 128) {
        const int b = tok0 + tid;
        float v[8];
        #pragma unroll
        for (int j = 0; j < 8; ++j) v[j] = Ls[tid][j];
        // top-2, ties -> lower index (matches jax.lax.top_k)
        int i0 = 0;
        #pragma unroll
        for (int j = 1; j < 8; ++j) if (v[j] > v[i0]) i0 = j;
        int i1 = (i0 == 0) ? 1 : 0;
        #pragma unroll
        for (int j = 0; j < 8; ++j) if (j != i0 && j != i1 && v[j] > v[i1]) i1 = j;
        const float t  = expf(v[i1] - v[i0]);   // <= 1
        const float w0 = 1.f / (1.f + t);
        const float w1 = t  / (1.f + t);
        int p0 = atomicAdd(&g_cnt[i0], 1);
        g_tok[i0 * NB + p0] = b; g_wt[i0 * NB + p0] = w0; g_slot[i0 * NB + p0] = 0;
        int p1 = atomicAdd(&g_cnt[i1], 1);
        g_tok[i1 * NB + p1] = b; g_wt[i1 * NB + p1] = w1; g_slot[i1 * NB + p1] = 1;
    }
}

// ---------------- per-expert SGEMM: 128x128x8, 256 threads, 8x8/thread -----
// LAYER 1: A = gathered x_e rows        -> relu -> g_h1
// LAYER 2: A = g_h1                     -> relu -> g_h2
// LAYER 3: A = g_h2 -> w*(acc+bias) scattered to g_part[slot][token]
template<int LAYER, int K, int N>
__global__ void __launch_bounds__(256)
expert_gemm(XPtrs xp, const float* __restrict__ W, const float* __restrict__ bias) {
    const int e   = blockIdx.z;
    const int cnt = g_cnt[e];
    const int m0  = blockIdx.y * 128;
    if (m0 >= cnt) return;
    const int n0  = blockIdx.x * 128;

    const float* __restrict__ Wb    = W    + (size_t)e * K * N;
    const float* __restrict__ biasb = bias + (size_t)e * N;

    __shared__ float As[8][132];   // [k][m], padded
    __shared__ float Bs[8][128];   // [k][n]

    const int tid = threadIdx.x;
    const int tx  = tid & 15;
    const int ty  = tid >> 4;

    const int lrowA = tid >> 1;          // 0..127
    const int lkA   = (tid & 1) * 4;     // 0 or 4
    const int lkB   = tid >> 5;          // 0..7
    const int lcB   = (tid & 31) * 4;    // 0..124

    // resolve this thread's A row pointer (clamped for out-of-count rows)
    const int  grow  = m0 + lrowA;
    const bool rowok = grow < cnt;
    const float* __restrict__ Arow;
    if (LAYER == 1) {
        int tok = rowok ? g_tok[e * NB + grow] : 0;
        Arow = xp.p[e] + (size_t)tok * K;
    } else {
        const float* Abase = (LAYER == 2) ? g_h1 : g_h2;
        Arow = Abase + ((size_t)e * NB + (rowok ? grow : 0)) * K;
    }

    float acc[8][8];
    #pragma unroll
    for (int i = 0; i < 8; ++i)
        #pragma unroll
        for (int j = 0; j < 8; ++j) acc[i][j] = 0.f;

    float4 pa = *(const float4*)&Arow[lkA];
    float4 pb = *(const float4*)&Wb[(size_t)lkB * N + n0 + lcB];

    const int ktiles = K / 8;
    for (int t = 0; t < ktiles; ++t) {
        As[lkA + 0][lrowA] = pa.x; As[lkA + 1][lrowA] = pa.y;
        As[lkA + 2][lrowA] = pa.z; As[lkA + 3][lrowA] = pa.w;
        *(float4*)&Bs[lkB][lcB] = pb;
        __syncthreads();
        if (t + 1 < ktiles) {
            int k0 = (t + 1) * 8;
            pa = *(const float4*)&Arow[k0 + lkA];
            pb = *(const float4*)&Wb[(size_t)(k0 + lkB) * N + n0 + lcB];
        }
        #pragma unroll
        for (int kk = 0; kk < 8; ++kk) {
            float4 a0 = *(const float4*)&As[kk][ty * 4];
            float4 a1 = *(const float4*)&As[kk][64 + ty * 4];
            float4 b0 = *(const float4*)&Bs[kk][tx * 4];
            float4 b1 = *(const float4*)&Bs[kk][64 + tx * 4];
            float av[8] = {a0.x, a0.y, a0.z, a0.w, a1.x, a1.y, a1.z, a1.w};
            float bv[8] = {b0.x, b0.y, b0.z, b0.w, b1.x, b1.y, b1.z, b1.w};
            #pragma unroll
            for (int i = 0; i < 8; ++i)
                #pragma unroll
                for (int j = 0; j < 8; ++j)
                    acc[i][j] = fmaf(av[i], bv[j], acc[i][j]);
        }
        __syncthreads();
    }

    // epilogue
    float bb[8];
    #pragma unroll
    for (int j = 0; j < 8; ++j) {
        int c = (j < 4) ? (tx * 4 + j) : (64 + tx * 4 + (j - 4));
        bb[j] = biasb[n0 + c];
    }
    #pragma unroll
    for (int i = 0; i < 8; ++i) {
        int r = (i < 4) ? (ty * 4 + i) : (64 + ty * 4 + (i - 4));
        if (m0 + r >= cnt) continue;
        if (LAYER == 3) {
            int   li   = e * NB + m0 + r;
            int   tok  = g_tok[li];
            float w    = g_wt[li];
            int   slot = g_slot[li];
            float* orow = g_part + ((size_t)slot * NB + tok) * NO + n0;
            float4 v0, v1;
            v0.x = w * (acc[i][0] + bb[0]); v0.y = w * (acc[i][1] + bb[1]);
            v0.z = w * (acc[i][2] + bb[2]); v0.w = w * (acc[i][3] + bb[3]);
            v1.x = w * (acc[i][4] + bb[4]); v1.y = w * (acc[i][5] + bb[5]);
            v1.z = w * (acc[i][6] + bb[6]); v1.w = w * (acc[i][7] + bb[7]);
            *(float4*)&orow[tx * 4]      = v0;
            *(float4*)&orow[64 + tx * 4] = v1;
        } else {
            float* hout = ((LAYER == 1) ? g_h1 : g_h2)
                        + ((size_t)e * NB + m0 + r) * N + n0;
            float4 v0, v1;
            v0.x = fmaxf(acc[i][0] + bb[0], 0.f); v0.y = fmaxf(acc[i][1] + bb[1], 0.f);
            v0.z = fmaxf(acc[i][2] + bb[2], 0.f); v0.w = fmaxf(acc[i][3] + bb[3], 0.f);
            v1.x = fmaxf(acc[i][4] + bb[4], 0.f); v1.y = fmaxf(acc[i][5] + bb[5], 0.f);
            v1.z = fmaxf(acc[i][6] + bb[6], 0.f); v1.w = fmaxf(acc[i][7] + bb[7], 0.f);
            *(float4*)&hout[tx * 4]      = v0;
            *(float4*)&hout[64 + tx * 4] = v1;
        }
    }
}

// ---------------- combine the two slots -> output --------------------------
__global__ void combine_kernel(float* __restrict__ out) {
    const size_t n4 = (size_t)NB * NO / 4;
    const float4* p0 = (const float4*)g_part;
    const float4* p1 = (const float4*)(g_part + (size_t)NB * NO);
    float4* o = (float4*)out;
    for (size_t i = blockIdx.x * blockDim.x + threadIdx.x; i < n4;
         i += (size_t)gridDim.x * blockDim.x) {
        float4 a = p0[i], b = p1[i];
        float4 r;
        r.x = a.x + b.x; r.y = a.y + b.y; r.z = a.z + b.z; r.w = a.w + b.w;
        o[i] = r;
    }
}

// ---------------- launch ----------------------------------------------------
extern "C" void kernel_launch(void* const* d_in, const int* in_sizes, int n_in,
                              void* d_out, int out_size) {
    XPtrs xp;
    for (int i = 0; i < NE; ++i) xp.p[i] = (const float*)d_in[i];
    const float* gw    = (const float*)d_in[8];
    const float* gb    = (const float*)d_in[9];
    const float* w_in  = (const float*)d_in[10];
    const float* b_in  = (const float*)d_in[11];
    const float* w_h   = (const float*)d_in[12];
    const float* b_h   = (const float*)d_in[13];
    const float* w_out = (const float*)d_in[14];
    const float* b_out = (const float*)d_in[15];
    float* out = (float*)d_out;

    reset_kernel<<<1, 32>>>();
    gate_kernel<<<NB / 128, 256>>>(xp, gw, gb);
    expert_gemm<1, ND, NH><<<dim3(NH / 128, NB / 128, NE), 256>>>(xp, w_in,  b_in);
    expert_gemm<2, NH, NH><<<dim3(NH / 128, NB / 128, NE), 256>>>(xp, w_h,   b_h);
    expert_gemm<3, NH, NO><<<dim3(NO / 128, NB / 128, NE), 256>>>(xp, w_out, b_out);
    combine_kernel<<<2048, 256>>>(out);
}

// round 10
// speedup vs baseline: 1.4999x; 1.4999x over previous
#include <cuda_runtime.h>
#include <math.h>
#include <stdint.h>

#define NE 8
#define ND 1024
#define NH 2048
#define NO 1024
#define NB 4096

// ---------------- scratch (device globals; no allocation allowed) ----------
__device__ int   g_cnt[NE];
__device__ int   g_tok [NE * NB];
__device__ float g_wt  [NE * NB];
__device__ int   g_slot[NE * NB];
__device__ float g_h1[(size_t)NE * NB * NH];
__device__ float g_h2[(size_t)NE * NB * NH];
__device__ float g_part[(size_t)2 * NB * NO];

struct XPtrs { const float* p[NE]; };

// ---------------- helpers ---------------------------------------------------
__device__ __forceinline__ uint32_t f2tf(float f) {
    uint32_t r;
    asm("cvt.rna.tf32.f32 %0, %1;" : "=r"(r) : "f"(f));
    return r;
}

__device__ __forceinline__ void mma_tf32(float* c, const uint32_t* a, uint32_t b0, uint32_t b1) {
    asm volatile(
        "mma.sync.aligned.m16n8k8.row.col.f32.tf32.tf32.f32 "
        "{%0,%1,%2,%3}, {%4,%5,%6,%7}, {%8,%9}, {%0,%1,%2,%3};"
        : "+f"(c[0]), "+f"(c[1]), "+f"(c[2]), "+f"(c[3])
        : "r"(a[0]), "r"(a[1]), "r"(a[2]), "r"(a[3]), "r"(b0), "r"(b1));
}

// ---------------- reset -----------------------------------------------------
__global__ void reset_kernel() {
    if (threadIdx.x < NE) g_cnt[threadIdx.x] = 0;
}

// ---------------- gating (validated round 1) --------------------------------
__global__ void __launch_bounds__(256)
gate_kernel(XPtrs xp, const float* __restrict__ gw, const float* __restrict__ gb) {
    __shared__ float Xs[64][129];
    __shared__ float Gs[64][8];
    __shared__ float Ls[128][8];

    const int tid   = threadIdx.x;
    const int token = tid & 127;
    const int half  = tid >> 7;
    const int tok0  = blockIdx.x * 128;

    float acc[4] = {0.f, 0.f, 0.f, 0.f};

    for (int e = 0; e < NE; ++e) {
        const float* __restrict__ xe = xp.p[e];
        for (int dc = 0; dc < ND; dc += 64) {
            #pragma unroll
            for (int i = 0; i < 8; ++i) {
                int idx = tid + i * 256;
                int r   = idx >> 4;
                int c   = (idx & 15) * 4;
                float4 v = *(const float4*)&xe[(size_t)(tok0 + r) * ND + dc + c];
                Xs[c + 0][r] = v.x; Xs[c + 1][r] = v.y;
                Xs[c + 2][r] = v.z; Xs[c + 3][r] = v.w;
            }
            if (tid < 128) {
                int r = tid >> 1;
                int c = (tid & 1) * 4;
                float4 v = *(const float4*)&gw[(size_t)(e * ND + dc + r) * NE + c];
                *(float4*)&Gs[r][c] = v;
            }
            __syncthreads();
            #pragma unroll 16
            for (int k = 0; k < 64; ++k) {
                float  a = Xs[k][token];
                float4 g = *(const float4*)&Gs[k][half * 4];
                acc[0] = fmaf(a, g.x, acc[0]);
                acc[1] = fmaf(a, g.y, acc[1]);
                acc[2] = fmaf(a, g.z, acc[2]);
                acc[3] = fmaf(a, g.w, acc[3]);
            }
            __syncthreads();
        }
    }
    #pragma unroll
    for (int j = 0; j < 4; ++j) Ls[token][half * 4 + j] = acc[j] + gb[half * 4 + j];
    __syncthreads();

    if (tid < 128) {
        const int b = tok0 + tid;
        float v[8];
        #pragma unroll
        for (int j = 0; j < 8; ++j) v[j] = Ls[tid][j];
        int i0 = 0;
        #pragma unroll
        for (int j = 1; j < 8; ++j) if (v[j] > v[i0]) i0 = j;
        int i1 = (i0 == 0) ? 1 : 0;
        #pragma unroll
        for (int j = 0; j < 8; ++j) if (j != i0 && j != i1 && v[j] > v[i1]) i1 = j;
        const float t  = expf(v[i1] - v[i0]);
        const float w0 = 1.f / (1.f + t);
        const float w1 = t  / (1.f + t);
        int p0 = atomicAdd(&g_cnt[i0], 1);
        g_tok[i0 * NB + p0] = b; g_wt[i0 * NB + p0] = w0; g_slot[i0 * NB + p0] = 0;
        int p1 = atomicAdd(&g_cnt[i1], 1);
        g_tok[i1 * NB + p1] = b; g_wt[i1 * NB + p1] = w1; g_slot[i1 * NB + p1] = 1;
    }
}

// ---------------- tf32 mma.sync expert GEMM ---------------------------------
// CTA tile 128(M) x 128(N) x 32(Kchunk); 8 warps, warp tile 32x64.
// A smem: [m][k] stride 36 words (conflict-free fragment loads).
// B smem: [k][n] stride 136 words (conflict-free fragment loads).
// Double-buffered, register prefetch, 1 sync per chunk.
#define A_STRIDE 36
#define B_STRIDE 136
#define A_BUF_W  (128 * A_STRIDE)          // 4608 words
#define B_BUF_W  (32 * B_STRIDE)           // 4352 words
#define SMEM_TOK_W 128
#define SMEM_WORDS (SMEM_TOK_W + 2 * A_BUF_W + 2 * B_BUF_W)   // 18048 words = 70.5 KB
#define SMEM_BYTES (SMEM_WORDS * 4)

template<int LAYER, int K, int N_TOTAL>
__global__ void __launch_bounds__(256)
expert_mma(XPtrs xp, const float* __restrict__ W, const float* __restrict__ bias) {
    const int e   = blockIdx.z;
    const int cnt = g_cnt[e];
    const int m0  = blockIdx.y * 128;
    if (m0 >= cnt) return;
    const int n0  = blockIdx.x * 128;

    extern __shared__ uint32_t smem[];
    int*      s_tok = (int*)smem;
    uint32_t* Abuf[2] = { smem + SMEM_TOK_W, smem + SMEM_TOK_W + A_BUF_W };
    uint32_t* Bbuf[2] = { smem + SMEM_TOK_W + 2 * A_BUF_W,
                          smem + SMEM_TOK_W + 2 * A_BUF_W + B_BUF_W };

    const int tid  = threadIdx.x;
    const int wid  = tid >> 5;
    const int lane = tid & 31;
    const int wm   = wid & 3;       // 4 warps over M (32 rows each)
    const int wn   = wid >> 2;      // 2 warps over N (64 cols each)
    const int grp  = lane >> 2;     // 0..7
    const int tig  = lane & 3;      // 0..3

    const float* __restrict__ Wb    = W    + (size_t)e * K * N_TOTAL;
    const float* __restrict__ biasb = bias + (size_t)e * N_TOTAL;

    if (LAYER == 1 && tid < 128) {
        int grow = m0 + tid;
        s_tok[tid] = g_tok[e * NB + ((grow < cnt) ? grow : (cnt - 1))];
    }
    __syncthreads();

    // ---- per-thread staging addresses --------------------------------------
    const float* aptr[4]; int saoff[4];
    const float* bptr[4]; int sboff[4];
    #pragma unroll
    for (int it = 0; it < 4; ++it) {
        int f4  = tid + it * 256;          // A: 1024 float4 (128 rows x 8)
        int row = f4 >> 3;
        int c4  = (f4 & 7) * 4;
        int rowc;
        if (LAYER == 1) {
            aptr[it] = xp.p[e] + (size_t)s_tok[row] * K + c4;
        } else {
            rowc = m0 + row; if (rowc >= cnt) rowc = cnt - 1;
            const float* src = (LAYER == 2) ? g_h1 : g_h2;
            aptr[it] = src + ((size_t)e * NB + rowc) * K + c4;
        }
        saoff[it] = row * A_STRIDE + c4;

        int g4  = tid + it * 256;          // B: 1024 float4 (32 k-rows x 32)
        int kr  = g4 >> 5;
        int nc4 = (g4 & 31) * 4;
        bptr[it] = Wb + (size_t)kr * N_TOTAL + n0 + nc4;
        sboff[it] = kr * B_STRIDE + nc4;
    }

    float acc[2][8][4];
    #pragma unroll
    for (int mt = 0; mt < 2; ++mt)
        #pragma unroll
        for (int nt = 0; nt < 8; ++nt)
            #pragma unroll
            for (int q = 0; q < 4; ++q) acc[mt][nt][q] = 0.f;

    const int T = K / 32;

    // prologue: stage chunk 0
    {
        #pragma unroll
        for (int it = 0; it < 4; ++it) {
            float4 v = *(const float4*)aptr[it];
            uint32_t* d = Abuf[0] + saoff[it];
            d[0] = f2tf(v.x); d[1] = f2tf(v.y); d[2] = f2tf(v.z); d[3] = f2tf(v.w);
        }
        #pragma unroll
        for (int it = 0; it < 4; ++it) {
            float4 v = *(const float4*)bptr[it];
            uint32_t* d = Bbuf[0] + sboff[it];
            d[0] = f2tf(v.x); d[1] = f2tf(v.y); d[2] = f2tf(v.z); d[3] = f2tf(v.w);
        }
    }
    __syncthreads();

    for (int t = 0; t < T; ++t) {
        const int buf = t & 1;
        float4 ra[4], rb[4];
        if (t + 1 < T) {
            const int ka = (t + 1) * 32;
            const size_t kb = (size_t)(t + 1) * 32 * N_TOTAL;
            #pragma unroll
            for (int it = 0; it < 4; ++it) ra[it] = *(const float4*)(aptr[it] + ka);
            #pragma unroll
            for (int it = 0; it < 4; ++it) rb[it] = *(const float4*)(bptr[it] + kb);
        }

        const uint32_t* As = Abuf[buf];
        const uint32_t* Bs = Bbuf[buf];
        #pragma unroll
        for (int kk = 0; kk < 4; ++kk) {
            uint32_t a[2][4];
            const int arow = wm * 32 + grp;
            const int acol = kk * 8 + tig;
            #pragma unroll
            for (int mt = 0; mt < 2; ++mt) {
                const uint32_t* ap = As + (arow + mt * 16) * A_STRIDE + acol;
                a[mt][0] = ap[0];
                a[mt][1] = ap[8 * A_STRIDE];
                a[mt][2] = ap[4];
                a[mt][3] = ap[8 * A_STRIDE + 4];
            }
            const int kbrow = kk * 8 + tig;
            #pragma unroll
            for (int nt = 0; nt < 8; ++nt) {
                const int nn = wn * 64 + nt * 8 + grp;
                uint32_t b0 = Bs[kbrow * B_STRIDE + nn];
                uint32_t b1 = Bs[(kbrow + 4) * B_STRIDE + nn];
                mma_tf32(acc[0][nt], a[0], b0, b1);
                mma_tf32(acc[1][nt], a[1], b0, b1);
            }
        }

        if (t + 1 < T) {
            const int nbuf = (t + 1) & 1;
            #pragma unroll
            for (int it = 0; it < 4; ++it) {
                uint32_t* d = Abuf[nbuf] + saoff[it];
                d[0] = f2tf(ra[it].x); d[1] = f2tf(ra[it].y);
                d[2] = f2tf(ra[it].z); d[3] = f2tf(ra[it].w);
            }
            #pragma unroll
            for (int it = 0; it < 4; ++it) {
                uint32_t* d = Bbuf[nbuf] + sboff[it];
                d[0] = f2tf(rb[it].x); d[1] = f2tf(rb[it].y);
                d[2] = f2tf(rb[it].z); d[3] = f2tf(rb[it].w);
            }
        }
        __syncthreads();
    }

    // ---- epilogue ----------------------------------------------------------
    #pragma unroll
    for (int mt = 0; mt < 2; ++mt) {
        #pragma unroll
        for (int hf = 0; hf < 2; ++hf) {
            const int r = m0 + wm * 32 + mt * 16 + grp + hf * 8;
            if (r >= cnt) continue;
            if (LAYER == 3) {
                const int   li   = e * NB + r;
                const int   tok  = g_tok[li];
                const float wgt  = g_wt[li];
                const int   slot = g_slot[li];
                float* orow = g_part + ((size_t)slot * NB + tok) * NO;
                #pragma unroll
                for (int nt = 0; nt < 8; ++nt) {
                    const int c = n0 + wn * 64 + nt * 8 + tig * 2;
                    float2 bv = *(const float2*)&biasb[c];
                    float2 v;
                    v.x = wgt * (acc[mt][nt][hf * 2 + 0] + bv.x);
                    v.y = wgt * (acc[mt][nt][hf * 2 + 1] + bv.y);
                    *(float2*)&orow[c] = v;
                }
            } else {
                float* hrow = ((LAYER == 1) ? g_h1 : g_h2)
                            + ((size_t)e * NB + r) * N_TOTAL;
                #pragma unroll
                for (int nt = 0; nt < 8; ++nt) {
                    const int c = n0 + wn * 64 + nt * 8 + tig * 2;
                    float2 bv = *(const float2*)&biasb[c];
                    float2 v;
                    v.x = fmaxf(acc[mt][nt][hf * 2 + 0] + bv.x, 0.f);
                    v.y = fmaxf(acc[mt][nt][hf * 2 + 1] + bv.y, 0.f);
                    *(float2*)&hrow[c] = v;
                }
            }
        }
    }
}

// ---------------- combine ----------------------------------------------------
__global__ void combine_kernel(float* __restrict__ out) {
    const size_t n4 = (size_t)NB * NO / 4;
    const float4* p0 = (const float4*)g_part;
    const float4* p1 = (const float4*)(g_part + (size_t)NB * NO);
    float4* o = (float4*)out;
    for (size_t i = blockIdx.x * blockDim.x + threadIdx.x; i < n4;
         i += (size_t)gridDim.x * blockDim.x) {
        float4 a = p0[i], b = p1[i];
        float4 r;
        r.x = a.x + b.x; r.y = a.y + b.y; r.z = a.z + b.z; r.w = a.w + b.w;
        o[i] = r;
    }
}

// ---------------- launch -----------------------------------------------------
extern "C" void kernel_launch(void* const* d_in, const int* in_sizes, int n_in,
                              void* d_out, int out_size) {
    XPtrs xp;
    for (int i = 0; i < NE; ++i) xp.p[i] = (const float*)d_in[i];
    const float* gw    = (const float*)d_in[8];
    const float* gb    = (const float*)d_in[9];
    const float* w_in  = (const float*)d_in[10];
    const float* b_in  = (const float*)d_in[11];
    const float* w_h   = (const float*)d_in[12];
    const float* b_h   = (const float*)d_in[13];
    const float* w_out = (const float*)d_in[14];
    const float* b_out = (const float*)d_in[15];
    float* out = (float*)d_out;

    cudaFuncSetAttribute(expert_mma<1, ND, NH>,
                         cudaFuncAttributeMaxDynamicSharedMemorySize, SMEM_BYTES);
    cudaFuncSetAttribute(expert_mma<2, NH, NH>,
                         cudaFuncAttributeMaxDynamicSharedMemorySize, SMEM_BYTES);
    cudaFuncSetAttribute(expert_mma<3, NH, NO>,
                         cudaFuncAttributeMaxDynamicSharedMemorySize, SMEM_BYTES);

    reset_kernel<<<1, 32>>>();
    gate_kernel<<<NB / 128, 256>>>(xp, gw, gb);
    expert_mma<1, ND, NH><<<dim3(NH / 128, NB / 128, NE), 256, SMEM_BYTES>>>(xp, w_in,  b_in);
    expert_mma<2, NH, NH><<<dim3(NH / 128, NB / 128, NE), 256, SMEM_BYTES>>>(xp, w_h,   b_h);
    expert_mma<3, NH, NO><<<dim3(NO / 128, NB / 128, NE), 256, SMEM_BYTES>>>(xp, w_out, b_out);
    combine_kernel<<<2048, 256>>>(out);
}

// round 12
// speedup vs baseline: 2.6782x; 1.7856x over previous
#include <cuda_runtime.h>
#include <math.h>
#include <stdint.h>

#define NE 8
#define ND 1024
#define NH 2048
#define NO 1024
#define NB 4096

// ---------------- scratch (device globals; no allocation allowed) ----------
__device__ int   g_cnt[NE];
__device__ int   g_tok [NE * NB];
__device__ float g_wt  [NE * NB];
__device__ int   g_slot[NE * NB];
__device__ float g_h1[(size_t)NE * NB * NH];            // 256 MB (tf32-rounded)
__device__ float g_h2[(size_t)NE * NB * NH];            // 256 MB (tf32-rounded)
__device__ float g_part[(size_t)2 * NB * NO];           // 32 MB
__device__ float g_xr   [(size_t)NE * NB * ND];         // 128 MB tf32-rounded x
__device__ float g_wrin [(size_t)NE * ND * NH];         // 64 MB
__device__ float g_wrh  [(size_t)NE * NH * NH];         // 128 MB
__device__ float g_wrout[(size_t)NE * NH * NO];         // 64 MB
__device__ float g_glog [(size_t)NE * NB * 8];          // gate partial logits

struct XPtrs { const float* p[NE]; };

// ---------------- helpers ---------------------------------------------------
__device__ __forceinline__ uint32_t f2tf(float f) {
    uint32_t r;
    asm("cvt.rna.tf32.f32 %0, %1;" : "=r"(r) : "f"(f));
    return r;
}
__device__ __forceinline__ float rtf(float f) { return __uint_as_float(f2tf(f)); }

__device__ __forceinline__ uint32_t smem_u32(const void* p) {
    uint32_t a;
    asm("{ .reg .u64 t; cvta.to.shared.u64 t, %1; cvt.u32.u64 %0, t; }" : "=r"(a) : "l"(p));
    return a;
}

__device__ __forceinline__ void mma_tf32(float* c, const uint32_t* a, uint32_t b0, uint32_t b1) {
    asm volatile(
        "mma.sync.aligned.m16n8k8.row.col.f32.tf32.tf32.f32 "
        "{%0,%1,%2,%3}, {%4,%5,%6,%7}, {%8,%9}, {%0,%1,%2,%3};"
        : "+f"(c[0]), "+f"(c[1]), "+f"(c[2]), "+f"(c[3])
        : "r"(a[0]), "r"(a[1]), "r"(a[2]), "r"(a[3]), "r"(b0), "r"(b1));
}

__device__ __forceinline__ void cpa16(uint32_t dst, const void* src) {
    asm volatile("cp.async.cg.shared.global [%0], [%1], 16;" :: "r"(dst), "l"(src));
}
#define CP_COMMIT() asm volatile("cp.async.commit_group;" ::: "memory")
#define CP_WAIT2()  asm volatile("cp.async.wait_group 2;" ::: "memory")

// ---------------- reset -----------------------------------------------------
__global__ void reset_kernel() {
    if (threadIdx.x < NE) g_cnt[threadIdx.x] = 0;
}

// ---------------- pre-round inputs to tf32 ----------------------------------
__global__ void __launch_bounds__(256)
round_x_kernel(XPtrs xp) {
    const size_t per = (size_t)NB * ND / 4;
    const size_t n4  = (size_t)NE * per;
    float4* dst = (float4*)g_xr;
    for (size_t i = (size_t)blockIdx.x * blockDim.x + threadIdx.x; i < n4;
         i += (size_t)gridDim.x * blockDim.x) {
        size_t e = i / per;
        float4 v = ((const float4*)xp.p[e])[i - e * per];
        v.x = rtf(v.x); v.y = rtf(v.y); v.z = rtf(v.z); v.w = rtf(v.w);
        dst[i] = v;
    }
}

__global__ void __launch_bounds__(256)
round_w_kernel(const float* __restrict__ W, int sel, size_t n4) {
    float* d = (sel == 0) ? g_wrin : (sel == 1) ? g_wrh : g_wrout;
    float4* dst = (float4*)d;
    const float4* src = (const float4*)W;
    for (size_t i = (size_t)blockIdx.x * blockDim.x + threadIdx.x; i < n4;
         i += (size_t)gridDim.x * blockDim.x) {
        float4 v = src[i];
        v.x = rtf(v.x); v.y = rtf(v.y); v.z = rtf(v.z); v.w = rtf(v.w);
        dst[i] = v;
    }
}

// ---------------- gating pass A: per-expert partial logits ------------------
// grid (32 token-blocks, 8 experts), 256 threads. Same inner math as the
// validated gate, restricted to one expert; partials summed in pass B.
__global__ void __launch_bounds__(256)
gatep_kernel(XPtrs xp, const float* __restrict__ gw) {
    __shared__ float Xs[64][129];
    __shared__ float Gs[64][8];

    const int tid   = threadIdx.x;
    const int token = tid & 127;
    const int half  = tid >> 7;
    const int tok0  = blockIdx.x * 128;
    const int e     = blockIdx.y;

    float acc[4] = {0.f, 0.f, 0.f, 0.f};
    const float* __restrict__ xe = xp.p[e];

    for (int dc = 0; dc < ND; dc += 64) {
        #pragma unroll
        for (int i = 0; i < 8; ++i) {
            int idx = tid + i * 256;
            int r   = idx >> 4;
            int c   = (idx & 15) * 4;
            float4 v = *(const float4*)&xe[(size_t)(tok0 + r) * ND + dc + c];
            Xs[c + 0][r] = v.x; Xs[c + 1][r] = v.y;
            Xs[c + 2][r] = v.z; Xs[c + 3][r] = v.w;
        }
        if (tid < 128) {
            int r = tid >> 1;
            int c = (tid & 1) * 4;
            float4 v = *(const float4*)&gw[(size_t)(e * ND + dc + r) * NE + c];
            *(float4*)&Gs[r][c] = v;
        }
        __syncthreads();
        #pragma unroll 16
        for (int k = 0; k < 64; ++k) {
            float  a = Xs[k][token];
            float4 g = *(const float4*)&Gs[k][half * 4];
            acc[0] = fmaf(a, g.x, acc[0]);
            acc[1] = fmaf(a, g.y, acc[1]);
            acc[2] = fmaf(a, g.z, acc[2]);
            acc[3] = fmaf(a, g.w, acc[3]);
        }
        __syncthreads();
    }
    float* out = &g_glog[((size_t)e * NB + tok0 + token) * 8 + half * 4];
    #pragma unroll
    for (int j = 0; j < 4; ++j) out[j] = acc[j];
}

// ---------------- gating pass B: reduce + top-2 + scatter -------------------
__global__ void __launch_bounds__(256)
top2_kernel(const float* __restrict__ gb) {
    const int b = blockIdx.x * 256 + threadIdx.x;
    if (b >= NB) return;
    float v[8] = {0.f, 0.f, 0.f, 0.f, 0.f, 0.f, 0.f, 0.f};
    #pragma unroll
    for (int e = 0; e < NE; ++e) {
        const float4* p = (const float4*)&g_glog[((size_t)e * NB + b) * 8];
        float4 a0 = p[0], a1 = p[1];
        v[0] += a0.x; v[1] += a0.y; v[2] += a0.z; v[3] += a0.w;
        v[4] += a1.x; v[5] += a1.y; v[6] += a1.z; v[7] += a1.w;
    }
    #pragma unroll
    for (int j = 0; j < 8; ++j) v[j] += gb[j];
    int i0 = 0;
    #pragma unroll
    for (int j = 1; j < 8; ++j) if (v[j] > v[i0]) i0 = j;
    int i1 = (i0 == 0) ? 1 : 0;
    #pragma unroll
    for (int j = 0; j < 8; ++j) if (j != i0 && j != i1 && v[j] > v[i1]) i1 = j;
    const float t  = expf(v[i1] - v[i0]);
    const float w0 = 1.f / (1.f + t);
    const float w1 = t  / (1.f + t);
    int p0 = atomicAdd(&g_cnt[i0], 1);
    g_tok[i0 * NB + p0] = b; g_wt[i0 * NB + p0] = w0; g_slot[i0 * NB + p0] = 0;
    int p1 = atomicAdd(&g_cnt[i1], 1);
    g_tok[i1 * NB + p1] = b; g_wt[i1 * NB + p1] = w1; g_slot[i1 * NB + p1] = 1;
}

// ---------------- tf32 mma.sync expert GEMM ---------------------------------
// CTA 256(M) x 128(N), 8 warps, warp tile 64x64 (wm 0..3, wn 0..1).
// K-chunk 32, 3-stage cp.async ring. Inputs pre-rounded to tf32 -> raw copy.
// A smem [m][k] stride 36 words; B smem [k][n] stride 136 words (conflict-free).
#define AST 36
#define BST 136
#define AWRD (256 * AST)                 // 9216 words / stage
#define BWRD (32 * BST)                  // 4352 words / stage
#define TOKW 256
#define STAGES 3
#define SMEM_WORDS (TOKW + STAGES * (AWRD + BWRD))   // 40960 words
#define SMEM_BYTES (SMEM_WORDS * 4)                  // 160 KB

template<int LAYER, int K, int N_TOTAL>
__global__ void __launch_bounds__(256, 1)
expert_mma(const float* __restrict__ bias) {
    const int e   = blockIdx.z;
    const int cnt = g_cnt[e];
    const int m0  = blockIdx.y * 256;
    if (m0 >= cnt) return;
    const int n0  = blockIdx.x * 128;

    extern __shared__ uint32_t sm[];
    int*      s_tok = (int*)sm;
    uint32_t* Asm   = sm + TOKW;
    uint32_t* Bsm   = sm + TOKW + STAGES * AWRD;
    const uint32_t suA = smem_u32(Asm);
    const uint32_t suB = smem_u32(Bsm);

    const int tid  = threadIdx.x;
    const int wid  = tid >> 5;
    const int lane = tid & 31;
    const int wm   = wid & 3;        // 4 warps over M (64 rows each)
    const int wn   = wid >> 2;       // 2 warps over N (64 cols each)
    const int grp  = lane >> 2;
    const int tig  = lane & 3;

    const float* __restrict__ Wsrc =
        ((LAYER == 1) ? g_wrin : (LAYER == 2) ? g_wrh : g_wrout)
        + (size_t)e * K * N_TOTAL;
    const float* __restrict__ biasb = bias + (size_t)e * N_TOTAL;

    if (LAYER == 1) {
        int grow = m0 + tid;
        s_tok[tid] = g_tok[e * NB + ((grow < cnt) ? grow : (cnt - 1))];
    }
    __syncthreads();

    // ---- per-thread cp.async source pointers + smem byte offsets -----------
    const float* asrc[8]; uint32_t adst[8];
    #pragma unroll
    for (int it = 0; it < 8; ++it) {
        int idx = tid + it * 256;          // 2048 float4 = 256 rows x 8
        int row = idx >> 3;
        int c4  = (idx & 7) * 4;
        if (LAYER == 1) {
            asrc[it] = g_xr + ((size_t)e * NB + s_tok[row]) * K + c4;
        } else {
            int rowc = m0 + row; if (rowc >= cnt) rowc = cnt - 1;
            const float* src = (LAYER == 2) ? g_h1 : g_h2;
            asrc[it] = src + ((size_t)e * NB + rowc) * K + c4;
        }
        adst[it] = suA + (uint32_t)(row * AST + c4) * 4u;
    }
    const float* bsrc[4]; uint32_t bdst[4];
    #pragma unroll
    for (int it = 0; it < 4; ++it) {
        int idx = tid + it * 256;          // 1024 float4 = 32 k-rows x 32
        int kr  = idx >> 5;
        int nc4 = (idx & 31) * 4;
        bsrc[it] = Wsrc + (size_t)kr * N_TOTAL + n0 + nc4;
        bdst[it] = suB + (uint32_t)(kr * BST + nc4) * 4u;
    }

    float acc[4][8][4];
    #pragma unroll
    for (int mt = 0; mt < 4; ++mt)
        #pragma unroll
        for (int nt = 0; nt < 8; ++nt)
            #pragma unroll
            for (int q = 0; q < 4; ++q) acc[mt][nt][q] = 0.f;

    const int T = K / 32;

    // stage s <- chunk k0
    #define STAGE(s, k0) do {                                              \
        const uint32_t ao = (uint32_t)(s) * (AWRD * 4u);                   \
        const uint32_t bo = (uint32_t)(s) * (BWRD * 4u);                   \
        _Pragma("unroll")                                                  \
        for (int it = 0; it < 8; ++it)                                     \
            cpa16(adst[it] + ao, asrc[it] + (k0));                         \
        _Pragma("unroll")                                                  \
        for (int it = 0; it < 4; ++it)                                     \
            cpa16(bdst[it] + bo, bsrc[it] + (size_t)(k0) * N_TOTAL);       \
    } while (0)

    STAGE(0, 0);  CP_COMMIT();
    STAGE(1, 32); CP_COMMIT();

    for (int t = 0; t < T; ++t) {
        if (t + 2 < T) {
            int s = (t + 2) % 3;
            STAGE(s, (t + 2) * 32);
        }
        CP_COMMIT();               // uniform group count (empty near tail)
        CP_WAIT2();                // stage t resident
        __syncthreads();

        const uint32_t* As = Asm + (t % 3) * AWRD;
        const uint32_t* Bs = Bsm + (t % 3) * BWRD;
        #pragma unroll
        for (int kk = 0; kk < 4; ++kk) {
            uint32_t a[4][4];
            const int abase = (wm * 64 + grp) * AST + kk * 8 + tig;
            #pragma unroll
            for (int mt = 0; mt < 4; ++mt) {
                const uint32_t* ap = As + abase + mt * 16 * AST;
                a[mt][0] = ap[0];
                a[mt][1] = ap[8 * AST];
                a[mt][2] = ap[4];
                a[mt][3] = ap[8 * AST + 4];
            }
            const int kbrow = kk * 8 + tig;
            #pragma unroll
            for (int nt = 0; nt < 8; ++nt) {
                const int nn = wn * 64 + nt * 8 + grp;
                uint32_t b0 = Bs[kbrow * BST + nn];
                uint32_t b1 = Bs[(kbrow + 4) * BST + nn];
                #pragma unroll
                for (int mt = 0; mt < 4; ++mt)
                    mma_tf32(acc[mt][nt], a[mt], b0, b1);
            }
        }
        __syncthreads();           // protect buf (t%3) before restage at t+1
    }
    #undef STAGE

    // ---- epilogue ----------------------------------------------------------
    #pragma unroll
    for (int mt = 0; mt < 4; ++mt) {
        #pragma unroll
        for (int hf = 0; hf < 2; ++hf) {
            const int r = m0 + wm * 64 + mt * 16 + grp + hf * 8;
            if (r >= cnt) continue;
            if (LAYER == 3) {
                const int   li   = e * NB + r;
                const int   tok  = g_tok[li];
                const float wgt  = g_wt[li];
                const int   slot = g_slot[li];
                float* orow = g_part + ((size_t)slot * NB + tok) * NO;
                #pragma unroll
                for (int nt = 0; nt < 8; ++nt) {
                    const int c = n0 + wn * 64 + nt * 8 + tig * 2;
                    float2 bv = *(const float2*)&biasb[c];
                    float2 v;
                    v.x = wgt * (acc[mt][nt][hf * 2 + 0] + bv.x);
                    v.y = wgt * (acc[mt][nt][hf * 2 + 1] + bv.y);
                    *(float2*)&orow[c] = v;
                }
            } else {
                float* hrow = ((LAYER == 1) ? g_h1 : g_h2)
                            + ((size_t)e * NB + r) * N_TOTAL;
                #pragma unroll
                for (int nt = 0; nt < 8; ++nt) {
                    const int c = n0 + wn * 64 + nt * 8 + tig * 2;
                    float2 bv = *(const float2*)&biasb[c];
                    float2 v;
                    v.x = rtf(fmaxf(acc[mt][nt][hf * 2 + 0] + bv.x, 0.f));
                    v.y = rtf(fmaxf(acc[mt][nt][hf * 2 + 1] + bv.y, 0.f));
                    *(float2*)&hrow[c] = v;
                }
            }
        }
    }
}

// ---------------- combine ----------------------------------------------------
__global__ void combine_kernel(float* __restrict__ out) {
    const size_t n4 = (size_t)NB * NO / 4;
    const float4* p0 = (const float4*)g_part;
    const float4* p1 = (const float4*)(g_part + (size_t)NB * NO);
    float4* o = (float4*)out;
    for (size_t i = blockIdx.x * blockDim.x + threadIdx.x; i < n4;
         i += (size_t)gridDim.x * blockDim.x) {
        float4 a = p0[i], b = p1[i];
        float4 r;
        r.x = a.x + b.x; r.y = a.y + b.y; r.z = a.z + b.z; r.w = a.w + b.w;
        o[i] = r;
    }
}

// ---------------- launch -----------------------------------------------------
extern "C" void kernel_launch(void* const* d_in, const int* in_sizes, int n_in,
                              void* d_out, int out_size) {
    XPtrs xp;
    for (int i = 0; i < NE; ++i) xp.p[i] = (const float*)d_in[i];
    const float* gw    = (const float*)d_in[8];
    const float* gb    = (const float*)d_in[9];
    const float* w_in  = (const float*)d_in[10];
    const float* b_in  = (const float*)d_in[11];
    const float* w_h   = (const float*)d_in[12];
    const float* b_h   = (const float*)d_in[13];
    const float* w_out = (const float*)d_in[14];
    const float* b_out = (const float*)d_in[15];
    float* out = (float*)d_out;

    cudaFuncSetAttribute(expert_mma<1, ND, NH>,
                         cudaFuncAttributeMaxDynamicSharedMemorySize, SMEM_BYTES);
    cudaFuncSetAttribute(expert_mma<2, NH, NH>,
                         cudaFuncAttributeMaxDynamicSharedMemorySize, SMEM_BYTES);
    cudaFuncSetAttribute(expert_mma<3, NH, NO>,
                         cudaFuncAttributeMaxDynamicSharedMemorySize, SMEM_BYTES);

    reset_kernel<<<1, 32>>>();
    round_x_kernel<<<1024, 256>>>(xp);
    round_w_kernel<<<1024, 256>>>(w_in,  0, (size_t)NE * ND * NH / 4);
    round_w_kernel<<<1024, 256>>>(w_h,   1, (size_t)NE * NH * NH / 4);
    round_w_kernel<<<1024, 256>>>(w_out, 2, (size_t)NE * NH * NO / 4);
    gatep_kernel<<<dim3(NB / 128, NE), 256>>>(xp, gw);
    top2_kernel<<<NB / 256, 256>>>(gb);
    expert_mma<1, ND, NH><<<dim3(NH / 128, NB / 256, NE), 256, SMEM_BYTES>>>(b_in);
    expert_mma<2, NH, NH><<<dim3(NH / 128, NB / 256, NE), 256, SMEM_BYTES>>>(b_h);
    expert_mma<3, NH, NO><<<dim3(NO / 128, NB / 256, NE), 256, SMEM_BYTES>>>(b_out);
    combine_kernel<<<2048, 256>>>(out);
}

// round 15
// speedup vs baseline: 3.1136x; 1.1626x over previous
#include <cuda_runtime.h>
#include <math.h>
#include <stdint.h>

#define NE 8
#define ND 1024
#define NH 2048
#define NO 1024
#define NB 4096

// ---------------- scratch (device globals; no allocation allowed) ----------
__device__ int   g_cnt[NE];
__device__ int   g_tok [NE * NB];
__device__ float g_wt  [NE * NB];
__device__ int   g_slot[NE * NB];
__device__ float g_h1[(size_t)NE * NB * NH];            // tf32-rounded
__device__ float g_h2[(size_t)NE * NB * NH];            // tf32-rounded
__device__ float g_part[(size_t)2 * NB * NO];
__device__ float g_xr   [(size_t)NE * NB * ND];         // tf32-rounded x (written by gate)
__device__ float g_wrin [(size_t)NE * ND * NH];
__device__ float g_wrh  [(size_t)NE * NH * NH];
__device__ float g_wrout[(size_t)NE * NH * NO];
__device__ float g_glog [(size_t)NE * NB * 8];

struct XPtrs { const float* p[NE]; };

// ---------------- helpers ---------------------------------------------------
__device__ __forceinline__ uint32_t f2tf(float f) {
    uint32_t r;
    asm("cvt.rna.tf32.f32 %0, %1;" : "=r"(r) : "f"(f));
    return r;
}
__device__ __forceinline__ float rtf(float f) { return __uint_as_float(f2tf(f)); }

__device__ __forceinline__ uint32_t smem_u32(const void* p) {
    uint32_t a;
    asm("{ .reg .u64 t; cvta.to.shared.u64 t, %1; cvt.u32.u64 %0, t; }" : "=r"(a) : "l"(p));
    return a;
}

__device__ __forceinline__ void mma_tf32(float* c, const uint32_t* a, uint32_t b0, uint32_t b1) {
    asm volatile(
        "mma.sync.aligned.m16n8k8.row.col.f32.tf32.tf32.f32 "
        "{%0,%1,%2,%3}, {%4,%5,%6,%7}, {%8,%9}, {%0,%1,%2,%3};"
        : "+f"(c[0]), "+f"(c[1]), "+f"(c[2]), "+f"(c[3])
        : "r"(a[0]), "r"(a[1]), "r"(a[2]), "r"(a[3]), "r"(b0), "r"(b1));
}

__device__ __forceinline__ void cpa16(uint32_t dst, const void* src) {
    asm volatile("cp.async.cg.shared.global [%0], [%1], 16;" :: "r"(dst), "l"(src));
}
#define CP_COMMIT() asm volatile("cp.async.commit_group;" ::: "memory")
#define CP_WAIT(n)  asm volatile("cp.async.wait_group %0;" :: "n"(n) : "memory")

// ---------------- reset -----------------------------------------------------
__global__ void reset_kernel() {
    if (threadIdx.x < NE) g_cnt[threadIdx.x] = 0;
}

// ---------------- weight pre-round to tf32 ----------------------------------
__global__ void __launch_bounds__(256)
round_w_kernel(const float* __restrict__ W, int sel, size_t n4) {
    float* d = (sel == 0) ? g_wrin : (sel == 1) ? g_wrh : g_wrout;
    float4* dst = (float4*)d;
    const float4* src = (const float4*)W;
    for (size_t i = (size_t)blockIdx.x * blockDim.x + threadIdx.x; i < n4;
         i += (size_t)gridDim.x * blockDim.x) {
        float4 v = src[i];
        v.x = rtf(v.x); v.y = rtf(v.y); v.z = rtf(v.z); v.w = rtf(v.w);
        dst[i] = v;
    }
}

// ---------------- gating pass A: partial logits + rounded-x emission --------
__global__ void __launch_bounds__(256)
gatep_kernel(XPtrs xp, const float* __restrict__ gw) {
    __shared__ float Xs[64][129];
    __shared__ float Gs[64][8];

    const int tid   = threadIdx.x;
    const int token = tid & 127;
    const int half  = tid >> 7;
    const int tok0  = blockIdx.x * 128;
    const int e     = blockIdx.y;

    float acc[4] = {0.f, 0.f, 0.f, 0.f};
    const float* __restrict__ xe = xp.p[e];

    for (int dc = 0; dc < ND; dc += 64) {
        #pragma unroll
        for (int i = 0; i < 8; ++i) {
            int idx = tid + i * 256;
            int r   = idx >> 4;
            int c   = (idx & 15) * 4;
            float4 v = *(const float4*)&xe[(size_t)(tok0 + r) * ND + dc + c];
            Xs[c + 0][r] = v.x; Xs[c + 1][r] = v.y;
            Xs[c + 2][r] = v.z; Xs[c + 3][r] = v.w;
            // emit tf32-rounded x (each element of x visited exactly once)
            float4 rv;
            rv.x = rtf(v.x); rv.y = rtf(v.y); rv.z = rtf(v.z); rv.w = rtf(v.w);
            *(float4*)&g_xr[((size_t)e * NB + tok0 + r) * ND + dc + c] = rv;
        }
        if (tid < 128) {
            int r = tid >> 1;
            int c = (tid & 1) * 4;
            float4 v = *(const float4*)&gw[(size_t)(e * ND + dc + r) * NE + c];
            *(float4*)&Gs[r][c] = v;
        }
        __syncthreads();
        #pragma unroll 16
        for (int k = 0; k < 64; ++k) {
            float  a = Xs[k][token];
            float4 g = *(const float4*)&Gs[k][half * 4];
            acc[0] = fmaf(a, g.x, acc[0]);
            acc[1] = fmaf(a, g.y, acc[1]);
            acc[2] = fmaf(a, g.z, acc[2]);
            acc[3] = fmaf(a, g.w, acc[3]);
        }
        __syncthreads();
    }
    float* out = &g_glog[((size_t)e * NB + tok0 + token) * 8 + half * 4];
    #pragma unroll
    for (int j = 0; j < 4; ++j) out[j] = acc[j];
}

// ---------------- gating pass B: reduce + top-2 + scatter -------------------
__global__ void __launch_bounds__(256)
top2_kernel(const float* __restrict__ gb) {
    const int b = blockIdx.x * 256 + threadIdx.x;
    if (b >= NB) return;
    float v[8] = {0.f, 0.f, 0.f, 0.f, 0.f, 0.f, 0.f, 0.f};
    #pragma unroll
    for (int e = 0; e < NE; ++e) {
        const float4* p = (const float4*)&g_glog[((size_t)e * NB + b) * 8];
        float4 a0 = p[0], a1 = p[1];
        v[0] += a0.x; v[1] += a0.y; v[2] += a0.z; v[3] += a0.w;
        v[4] += a1.x; v[5] += a1.y; v[6] += a1.z; v[7] += a1.w;
    }
    #pragma unroll
    for (int j = 0; j < 8; ++j) v[j] += gb[j];
    int i0 = 0;
    #pragma unroll
    for (int j = 1; j < 8; ++j) if (v[j] > v[i0]) i0 = j;
    int i1 = (i0 == 0) ? 1 : 0;
    #pragma unroll
    for (int j = 0; j < 8; ++j) if (j != i0 && j != i1 && v[j] > v[i1]) i1 = j;
    const float t  = expf(v[i1] - v[i0]);
    const float w0 = 1.f / (1.f + t);
    const float w1 = t  / (1.f + t);
    int p0 = atomicAdd(&g_cnt[i0], 1);
    g_tok[i0 * NB + p0] = b; g_wt[i0 * NB + p0] = w0; g_slot[i0 * NB + p0] = 0;
    int p1 = atomicAdd(&g_cnt[i1], 1);
    g_tok[i1 * NB + p1] = b; g_wt[i1 * NB + p1] = w1; g_slot[i1 * NB + p1] = 1;
}

// ---------------- tf32 mma.sync expert GEMM ---------------------------------
// CTA 128(M) x 256(N), 8 warps, warp tile 64x64 (wm 0..1, wn 0..3).
// K-chunk 32, 4-stage cp.async ring, ONE sync per chunk.
// A smem [m][k] stride 36; B smem [k][n] stride 264 (both conflict-free).
#define AST 36
#define BST 264
#define AWRD (128 * AST)                 // 4608 words / stage
#define BWRD (32 * BST)                  // 8448 words / stage
#define TOKW 128
#define STAGES 4
#define SMEM_WORDS (TOKW + STAGES * (AWRD + BWRD))   // 52352 words
#define SMEM_BYTES (SMEM_WORDS * 4)                  // 209,408 B

template<int LAYER, int K, int N_TOTAL>
__global__ void __launch_bounds__(256, 1)
expert_mma(const float* __restrict__ bias) {
    const int e   = blockIdx.z;
    const int cnt = g_cnt[e];
    const int m0  = blockIdx.y * 128;
    if (m0 >= cnt) return;
    const int n0  = blockIdx.x * 256;

    extern __shared__ uint32_t sm[];
    int*      s_tok = (int*)sm;
    uint32_t* Asm   = sm + TOKW;
    uint32_t* Bsm   = sm + TOKW + STAGES * AWRD;
    const uint32_t suA = smem_u32(Asm);
    const uint32_t suB = smem_u32(Bsm);

    const int tid  = threadIdx.x;
    const int wid  = tid >> 5;
    const int lane = tid & 31;
    const int wm   = wid & 1;        // 2 warps over M (64 rows each)
    const int wn   = wid >> 1;       // 4 warps over N (64 cols each)
    const int grp  = lane >> 2;
    const int tig  = lane & 3;

    const float* __restrict__ Wsrc =
        ((LAYER == 1) ? g_wrin : (LAYER == 2) ? g_wrh : g_wrout)
        + (size_t)e * K * N_TOTAL;
    const float* __restrict__ biasb = bias + (size_t)e * N_TOTAL;

    if (LAYER == 1) {
        if (tid < 128) {
            int grow = m0 + tid;
            s_tok[tid] = g_tok[e * NB + ((grow < cnt) ? grow : (cnt - 1))];
        }
        __syncthreads();
    }

    // ---- per-thread cp.async source pointers + smem byte offsets -----------
    const float* asrc[4]; uint32_t adst[4];
    #pragma unroll
    for (int it = 0; it < 4; ++it) {
        int idx = tid + it * 256;          // 1024 float4 = 128 rows x 8
        int row = idx >> 3;
        int c4  = (idx & 7) * 4;
        if (LAYER == 1) {
            asrc[it] = g_xr + ((size_t)e * NB + s_tok[row]) * K + c4;
        } else {
            int rowc = m0 + row; if (rowc >= cnt) rowc = cnt - 1;
            const float* src = (LAYER == 2) ? g_h1 : g_h2;
            asrc[it] = src + ((size_t)e * NB + rowc) * K + c4;
        }
        adst[it] = suA + (uint32_t)(row * AST + c4) * 4u;
    }
    const float* bsrc[8]; uint32_t bdst[8];
    #pragma unroll
    for (int it = 0; it < 8; ++it) {
        int idx = tid + it * 256;          // 2048 float4 = 32 k-rows x 64
        int kr  = idx >> 6;
        int nc4 = (idx & 63) * 4;
        bsrc[it] = Wsrc + (size_t)kr * N_TOTAL + n0 + nc4;
        bdst[it] = suB + (uint32_t)(kr * BST + nc4) * 4u;
    }

    float acc[4][8][4];
    #pragma unroll
    for (int mt = 0; mt < 4; ++mt)
        #pragma unroll
        for (int nt = 0; nt < 8; ++nt)
            #pragma unroll
            for (int q = 0; q < 4; ++q) acc[mt][nt][q] = 0.f;

    const int T = K / 32;

    #define STAGE(s, k0) do {                                              \
        const uint32_t ao = (uint32_t)(s) * (AWRD * 4u);                   \
        const uint32_t bo = (uint32_t)(s) * (BWRD * 4u);                   \
        _Pragma("unroll")                                                  \
        for (int it = 0; it < 4; ++it)                                     \
            cpa16(adst[it] + ao, asrc[it] + (k0));                         \
        _Pragma("unroll")                                                  \
        for (int it = 0; it < 8; ++it)                                     \
            cpa16(bdst[it] + bo, bsrc[it] + (size_t)(k0) * N_TOTAL);       \
    } while (0)

    STAGE(0, 0);  CP_COMMIT();
    STAGE(1, 32); CP_COMMIT();
    STAGE(2, 64); CP_COMMIT();

    for (int t = 0; t < T; ++t) {
        CP_WAIT(2);                 // stage t resident (groups retire in order)
        __syncthreads();            // all warps see stage t; all done with t-1
        if (t + 3 < T) STAGE((t + 3) & 3, (t + 3) * 32);
        CP_COMMIT();                // uniform group count (empty near tail)

        const uint32_t* As = Asm + (t & 3) * AWRD;
        const uint32_t* Bs = Bsm + (t & 3) * BWRD;
        #pragma unroll
        for (int kk = 0; kk < 4; ++kk) {
            uint32_t a[4][4];
            const int abase = (wm * 64 + grp) * AST + kk * 8 + tig;
            #pragma unroll
            for (int mt = 0; mt < 4; ++mt) {
                const uint32_t* ap = As + abase + mt * 16 * AST;
                a[mt][0] = ap[0];
                a[mt][1] = ap[8 * AST];
                a[mt][2] = ap[4];
                a[mt][3] = ap[8 * AST + 4];
            }
            const int kbrow = kk * 8 + tig;
            #pragma unroll
            for (int nt = 0; nt < 8; ++nt) {
                const int nn = wn * 64 + nt * 8 + grp;
                uint32_t b0 = Bs[kbrow * BST + nn];
                uint32_t b1 = Bs[(kbrow + 4) * BST + nn];
                #pragma unroll
                for (int mt = 0; mt < 4; ++mt)
                    mma_tf32(acc[mt][nt], a[mt], b0, b1);
            }
        }
    }
    #undef STAGE

    // ---- epilogue ----------------------------------------------------------
    #pragma unroll
    for (int mt = 0; mt < 4; ++mt) {
        #pragma unroll
        for (int hf = 0; hf < 2; ++hf) {
            const int r = m0 + wm * 64 + mt * 16 + grp + hf * 8;
            if (r >= cnt) continue;
            if (LAYER == 3) {
                const int   li   = e * NB + r;
                const int   tok  = g_tok[li];
                const float wgt  = g_wt[li];
                const int   slot = g_slot[li];
                float* orow = g_part + ((size_t)slot * NB + tok) * NO;
                #pragma unroll
                for (int nt = 0; nt < 8; ++nt) {
                    const int c = n0 + wn * 64 + nt * 8 + tig * 2;
                    float2 bv = *(const float2*)&biasb[c];
                    float2 v;
                    v.x = wgt * (acc[mt][nt][hf * 2 + 0] + bv.x);
                    v.y = wgt * (acc[mt][nt][hf * 2 + 1] + bv.y);
                    *(float2*)&orow[c] = v;
                }
            } else {
                float* hrow = ((LAYER == 1) ? g_h1 : g_h2)
                            + ((size_t)e * NB + r) * N_TOTAL;
                #pragma unroll
                for (int nt = 0; nt < 8; ++nt) {
                    const int c = n0 + wn * 64 + nt * 8 + tig * 2;
                    float2 bv = *(const float2*)&biasb[c];
                    float2 v;
                    v.x = rtf(fmaxf(acc[mt][nt][hf * 2 + 0] + bv.x, 0.f));
                    v.y = rtf(fmaxf(acc[mt][nt][hf * 2 + 1] + bv.y, 0.f));
                    *(float2*)&hrow[c] = v;
                }
            }
        }
    }
}

// ---------------- combine ----------------------------------------------------
__global__ void combine_kernel(float* __restrict__ out) {
    const size_t n4 = (size_t)NB * NO / 4;
    const float4* p0 = (const float4*)g_part;
    const float4* p1 = (const float4*)(g_part + (size_t)NB * NO);
    float4* o = (float4*)out;
    for (size_t i = blockIdx.x * blockDim.x + threadIdx.x; i < n4;
         i += (size_t)gridDim.x * blockDim.x) {
        float4 a = p0[i], b = p1[i];
        float4 r;
        r.x = a.x + b.x; r.y = a.y + b.y; r.z = a.z + b.z; r.w = a.w + b.w;
        o[i] = r;
    }
}

// ---------------- launch -----------------------------------------------------
extern "C" void kernel_launch(void* const* d_in, const int* in_sizes, int n_in,
                              void* d_out, int out_size) {
    XPtrs xp;
    for (int i = 0; i < NE; ++i) xp.p[i] = (const float*)d_in[i];
    const float* gw    = (const float*)d_in[8];
    const float* gb    = (const float*)d_in[9];
    const float* w_in  = (const float*)d_in[10];
    const float* b_in  = (const float*)d_in[11];
    const float* w_h   = (const float*)d_in[12];
    const float* b_h   = (const float*)d_in[13];
    const float* w_out = (const float*)d_in[14];
    const float* b_out = (const float*)d_in[15];
    float* out = (float*)d_out;

    cudaFuncSetAttribute(expert_mma<1, ND, NH>,
                         cudaFuncAttributeMaxDynamicSharedMemorySize, SMEM_BYTES);
    cudaFuncSetAttribute(expert_mma<2, NH, NH>,
                         cudaFuncAttributeMaxDynamicSharedMemorySize, SMEM_BYTES);
    cudaFuncSetAttribute(expert_mma<3, NH, NO>,
                         cudaFuncAttributeMaxDynamicSharedMemorySize, SMEM_BYTES);

    reset_kernel<<<1, 32>>>();
    round_w_kernel<<<1024, 256>>>(w_in,  0, (size_t)NE * ND * NH / 4);
    round_w_kernel<<<1024, 256>>>(w_h,   1, (size_t)NE * NH * NH / 4);
    round_w_kernel<<<1024, 256>>>(w_out, 2, (size_t)NE * NH * NO / 4);
    gatep_kernel<<<dim3(NB / 128, NE), 256>>>(xp, gw);
    top2_kernel<<<NB / 256, 256>>>(gb);
    expert_mma<1, ND, NH><<<dim3(NH / 256, NB / 128, NE), 256, SMEM_BYTES>>>(b_in);
    expert_mma<2, NH, NH><<<dim3(NH / 256, NB / 128, NE), 256, SMEM_BYTES>>>(b_h);
    expert_mma<3, NH, NO><<<dim3(NO / 256, NB / 128, NE), 256, SMEM_BYTES>>>(b_out);
    combine_kernel<<<2048, 256>>>(out);
}